// round 5
// baseline (speedup 1.0000x reference)
#include <cuda_runtime.h>
#include <cuda_fp16.h>
#include <cuda_fp8.h>

#define TT 256
#define CC 56
#define HH 1024
#define NBLK 148
#define NTHR 1024
#define INV_WSCALE (1.0f/64.0f)

// ---------------- quantized weights (filled by convert_kernel each launch) ----
__device__ __align__(16) unsigned char w8_Wih_mid[(size_t)4*4096*2048];
__device__ __align__(16) unsigned char w8_Whh_mid[(size_t)4*4096*1024];
__device__ __align__(16) unsigned char w8_Wih_top[(size_t)4096*1024];
__device__ __align__(16) unsigned char w8_Whh_top[(size_t)4096*1024];
__device__ __align__(16) __half h_Wmid[(size_t)4*1024*1024];
__device__ __align__(16) __half h_Vmid[(size_t)4*1024*1024];
__device__ __align__(16) __half h_V1[(size_t)56*1024];
__device__ __align__(16) __half h_W0[(size_t)1024*56];

// ---------------- state / scratch ----------------------------------------------
// g_xin[m] = [BU(1024) | TD_prev(1024) | h_prev(1024)] halves, contiguous per layer
__device__ __align__(16) __half g_xin[4][3*HH];
__device__ __align__(16) __half g_xtop[2*HH];      // [BU5 | h5_prev]
__device__ float g_c[2][5][HH];
__device__ float g_reconR[4][HH];
__device__ float g_recon1[CC];
__device__ float g_z[4*HH];
__device__ float g_loss_parts[TT][5];
__device__ unsigned g_arrive[NBLK];

// ---------------- helpers -----------------------------------------------------
__device__ __forceinline__ float ldf(const float* p) { return __ldcg(p); }
__device__ __forceinline__ void  stf(float* p, float v) { __stcg(p, v); }

__device__ __forceinline__ float warp_red(float v) {
#pragma unroll
    for (int o = 16; o; o >>= 1) v += __shfl_xor_sync(0xffffffffu, v, o);
    return v;
}

__device__ __forceinline__ __half2 cvt8(unsigned v16) {
    __half2_raw r = __nv_cvt_fp8x2_to_halfraw2((__nv_fp8x2_storage_t)v16, __NV_E4M3);
    return *reinterpret_cast<__half2*>(&r);
}
__device__ __forceinline__ float hsum(__half2 h) {
    float2 f = __half22float2(h);
    return f.x + f.y;
}

// fp8 weights dot fp16 x (smem). NB = row bytes (1024 or 2048), fully unrolled.
template<int NB>
__device__ __forceinline__ float dot8(const unsigned char* __restrict__ w,
                                      const __half* __restrict__ x, int lane) {
    float acc = 0.f;
#pragma unroll
    for (int it = 0; it < NB / 512; it++) {
        int c = it * 512 + lane * 16;
        uint4 wv  = *reinterpret_cast<const uint4*>(w + c);
        uint4 xv0 = *reinterpret_cast<const uint4*>(reinterpret_cast<const char*>(x) + 2 * c);
        uint4 xv1 = *reinterpret_cast<const uint4*>(reinterpret_cast<const char*>(x) + 2 * c + 16);
        const __half2* xa = reinterpret_cast<const __half2*>(&xv0);
        const __half2* xb = reinterpret_cast<const __half2*>(&xv1);
        __half2 s = __floats2half2_rn(0.f, 0.f);
        s = __hfma2(cvt8(wv.x & 0xffffu), xa[0], s);
        s = __hfma2(cvt8(wv.x >> 16),     xa[1], s);
        s = __hfma2(cvt8(wv.y & 0xffffu), xa[2], s);
        s = __hfma2(cvt8(wv.y >> 16),     xa[3], s);
        s = __hfma2(cvt8(wv.z & 0xffffu), xb[0], s);
        s = __hfma2(cvt8(wv.z >> 16),     xb[1], s);
        s = __hfma2(cvt8(wv.w & 0xffffu), xb[2], s);
        s = __hfma2(cvt8(wv.w >> 16),     xb[3], s);
        acc += hsum(s);
    }
    return acc;
}

// fp16 weights dot fp16 x (smem). NB = row bytes (2048), fully unrolled.
template<int NB>
__device__ __forceinline__ float dot16(const __half* __restrict__ w,
                                       const __half* __restrict__ x, int lane) {
    float acc = 0.f;
#pragma unroll
    for (int it = 0; it < NB / 512; it++) {
        int c = it * 512 + lane * 16;
        uint4 wv = *reinterpret_cast<const uint4*>(reinterpret_cast<const char*>(w) + c);
        uint4 xv = *reinterpret_cast<const uint4*>(reinterpret_cast<const char*>(x) + c);
        const __half2* wa = reinterpret_cast<const __half2*>(&wv);
        const __half2* xa = reinterpret_cast<const __half2*>(&xv);
        __half2 s = __floats2half2_rn(0.f, 0.f);
        s = __hfma2(wa[0], xa[0], s);
        s = __hfma2(wa[1], xa[1], s);
        s = __hfma2(wa[2], xa[2], s);
        s = __hfma2(wa[3], xa[3], s);
        acc += hsum(s);
    }
    return acc;
}

// 56-wide dot: fp16 weights, fp32 x (smem)
__device__ __forceinline__ float dot56h(const __half* __restrict__ w,
                                        const float* __restrict__ x, int lane) {
    float acc = 0.f;
    if (lane < 28) {
        __half2 h = *reinterpret_cast<const __half2*>(w + lane * 2);
        float2 f = __half22float2(h);
        acc = f.x * x[lane * 2] + f.y * x[lane * 2 + 1];
    }
    return acc;
}

__device__ __forceinline__ float sigm(float x) { return 1.f / (1.f + __expf(-x)); }

// GPU-scope release/acquire grid barrier (no sys-scope volatiles, no threadfence).
__device__ __forceinline__ void gsync(unsigned ep) {
    __syncthreads();
    if (threadIdx.x < 32) {
        if (threadIdx.x == 0)
            asm volatile("st.release.gpu.global.b32 [%0], %1;"
                         :: "l"(g_arrive + blockIdx.x), "r"(ep) : "memory");
        const int lane = threadIdx.x;
        bool done = false;
        while (!done) {
            bool ok = true;
#pragma unroll
            for (int j = 0; j < 5; j++) {
                int s = lane + j * 32;
                if (s < NBLK) {
                    unsigned v;
                    asm volatile("ld.acquire.gpu.global.b32 %0, [%1];"
                                 : "=r"(v) : "l"(g_arrive + s) : "memory");
                    ok &= ((int)(v - ep) >= 0);
                }
            }
            done = __all_sync(0xffffffffu, ok);
        }
    }
    __syncthreads();
}

__device__ __forceinline__ float block_sum(float v, float* sred) {
    int lane = threadIdx.x & 31, w = threadIdx.x >> 5;
    v = warp_red(v);
    if (lane == 0) sred[w] = v;
    __syncthreads();
    float r = 0.f;
    if (w == 0) {
        r = (lane < NTHR / 32) ? sred[lane] : 0.f;
        r = warp_red(r);
    }
    __syncthreads();
    return r;   // valid in warp 0
}

// ---------------- conversion pre-pass ------------------------------------------
__global__ void convert_kernel(const float* __restrict__ W0, const float* __restrict__ Wmid,
                               const float* __restrict__ V1, const float* __restrict__ Vmid,
                               const float* __restrict__ Wihm, const float* __restrict__ Whhm,
                               const float* __restrict__ Wiht, const float* __restrict__ Whht) {
    long i0 = (long)blockIdx.x * blockDim.x + threadIdx.x;
    long st = (long)gridDim.x * blockDim.x;
#define CVT16(dst, src, n)                                                     \
    for (long i = i0; i < (long)(n) / 2; i += st)                              \
        ((__half2*)(dst))[i] = __float22half2_rn(((const float2*)(src))[i]);
#define CVT8(dst, src, n)                                                      \
    for (long i = i0; i < (long)(n) / 4; i += st) {                            \
        float4 v = ((const float4*)(src))[i];                                  \
        unsigned lo = (unsigned)__nv_cvt_float2_to_fp8x2(                      \
            make_float2(v.x * 64.f, v.y * 64.f), __NV_SATFINITE, __NV_E4M3);   \
        unsigned hi = (unsigned)__nv_cvt_float2_to_fp8x2(                      \
            make_float2(v.z * 64.f, v.w * 64.f), __NV_SATFINITE, __NV_E4M3);   \
        ((unsigned*)(dst))[i] = lo | (hi << 16);                               \
    }
    CVT8(w8_Wih_mid, Wihm, 4L * 4096 * 2048)
    CVT8(w8_Whh_mid, Whhm, 4L * 4096 * 1024)
    CVT8(w8_Wih_top, Wiht, 4096L * 1024)
    CVT8(w8_Whh_top, Whht, 4096L * 1024)
    CVT16(h_Wmid, Wmid, 4L * 1024 * 1024)
    CVT16(h_Vmid, Vmid, 4L * 1024 * 1024)
    CVT16(h_V1, V1, 56L * 1024)
    CVT16(h_W0, W0, 1024L * 56)
#undef CVT16
#undef CVT8
}

// ---------------- main persistent kernel ----------------------------------------
__global__ void __launch_bounds__(NTHR, 1)
predcells_kernel(const float* __restrict__ x_seq,
                 const float* __restrict__ W0_b,  const float* __restrict__ Wmid_b,
                 const float* __restrict__ V1_b,  const float* __restrict__ Vmid_b,
                 const float* __restrict__ bmid,  const float* __restrict__ btop,
                 float* __restrict__ out) {
    __shared__ __align__(16) __half sxh[3 * HH];
    __shared__ __align__(16) __half sTDh[HH];
    __shared__ __align__(16) __half shh[HH];
    __shared__ float sxf[64];
    __shared__ float sred[32];

    const int tid  = threadIdx.x;
    const int lane = tid & 31;
    const int wid  = tid >> 5;
    const int gw   = blockIdx.x * (NTHR / 32) + wid;
    const long gtid = (long)blockIdx.x * NTHR + tid;
    const long gsz  = (long)NBLK * NTHR;

    unsigned ep = g_arrive[blockIdx.x];   // all slots equal at entry

    // ---- prologue: zero carries, TD0/BU1 for t=0, loss0(t=0) ----
    const __half hz = __float2half_rn(0.f);
    for (long i = gtid; i < 5 * HH; i += gsz) { int l = (int)(i >> 10), k = (int)(i & 1023); g_c[0][l][k] = 0.f; }
    for (long i = gtid; i < 4 * HH; i += gsz) {
        int l = (int)(i >> 10), k = (int)(i & 1023);
        g_xin[l][HH + k] = hz; g_xin[l][2 * HH + k] = hz;   // TD_prev, h_prev = 0
        g_reconR[l][k] = 0.f;
    }
    for (long i = gtid; i < HH; i += gsz) g_xtop[HH + i] = hz;
    for (long i = gtid; i < CC; i += gsz) g_recon1[i] = 0.f;
    if (tid < CC) sxf[tid] = fabsf(x_seq[tid]);      // TD0(t=0) = |x_0|
    __syncthreads();
    if (gw < HH) {
        float a = warp_red(dot56h(&h_W0[(size_t)gw * CC], sxf, lane));
        if (lane == 0) g_xin[0][gw] = __float2half_rn(a + W0_b[gw]);
    }
    if (blockIdx.x == 0) {
        float s = block_sum((tid < CC) ? sxf[tid] : 0.f, sred);
        if (tid == 0) stf(&g_loss_parts[0][0], s);
    }
    gsync(++ep);

    for (int t = 0; t < TT; t++) {
        const int p = t & 1;

#pragma unroll 1
        for (int m = 0; m < 4; m++) {
            // ---- LSTM phase m: z = Wih·[BU;TD_prev] + Whh·h_prev + b ----
            if (tid < 384)
                reinterpret_cast<uint4*>(sxh)[tid] =
                    __ldcg(reinterpret_cast<const uint4*>(g_xin[m]) + tid);
            __syncthreads();
            if (gw < 4096) {
                const unsigned char* wih = w8_Wih_mid + ((size_t)m * 4096 + gw) * 2048;
                const unsigned char* whh = w8_Whh_mid + ((size_t)m * 4096 + gw) * 1024;
                float a = dot8<2048>(wih, sxh, lane)
                        + dot8<1024>(whh, sxh + 2 * HH, lane);
                a = warp_red(a);
                if (lane == 0) stf(&g_z[gw], a * INV_WSCALE + bmid[m * 4096 + gw]);
            }
            gsync(++ep);

            // ---- X phase m: gates, TD, BU = Wmid·TD, recon ----
            float td_val;
            {
                const int k = tid;
                float zi = ldf(&g_z[k]),          zf = ldf(&g_z[HH + k]);
                float zg = ldf(&g_z[2 * HH + k]), zo = ldf(&g_z[3 * HH + k]);
                float c_old = ldf(&g_c[p][m][k]);
                float cn = sigm(zf) * c_old + sigm(zi) * tanhf(zg);
                float hn = sigm(zo) * tanhf(cn);
                td_val = fabsf(hn - ldf(&g_reconR[m][k]));
                __half tdh = __float2half_rn(td_val);
                __half hnh = __float2half_rn(hn);
                sTDh[k] = tdh;
                shh[k]  = hnh;
                if (blockIdx.x == 0) {
                    stf(&g_c[1 - p][m][k], cn);
                    g_xin[m][HH + k]     = tdh;   // TD carry for next step
                    g_xin[m][2 * HH + k] = hnh;   // h carry for next step
                }
            }
            __syncthreads();
            const int nrec = (m == 0) ? CC : HH;
            if (gw < HH) {
                float a = warp_red(dot16<2048>(&h_Wmid[((size_t)m * HH + gw) * HH], sTDh, lane));
                __half r = __float2half_rn(a + Wmid_b[m * HH + gw]);
                if (lane == 0) { if (m < 3) g_xin[m + 1][gw] = r; else g_xtop[gw] = r; }
            } else if (gw < HH + nrec) {
                int r = gw - HH;
                if (m == 0) {
                    float a = warp_red(dot16<2048>(&h_V1[(size_t)r * HH], shh, lane));
                    if (lane == 0) stf(&g_recon1[r], a + V1_b[r]);
                } else {
                    float a = warp_red(dot16<2048>(&h_Vmid[((size_t)(m - 1) * HH + r) * HH], shh, lane));
                    if (lane == 0) stf(&g_reconR[m - 1][r], a + Vmid_b[(m - 1) * HH + r]);
                }
            }
            if (blockIdx.x == 0) {
                float s = block_sum(td_val, sred);
                if (tid == 0) stf(&g_loss_parts[t][1 + m], s);
            }
            gsync(++ep);
        }

        // ---- top LSTM phase: z = Wih_top·BU5 + Whh_top·h5_prev + b ----
        if (tid < 256)
            reinterpret_cast<uint4*>(sxh)[tid] =
                __ldcg(reinterpret_cast<const uint4*>(g_xtop) + tid);
        __syncthreads();
        if (gw < 4096) {
            float a = dot8<1024>(w8_Wih_top + (size_t)gw * 1024, sxh, lane)
                    + dot8<1024>(w8_Whh_top + (size_t)gw * 1024, sxh + HH, lane);
            a = warp_red(a);
            if (lane == 0) stf(&g_z[gw], a * INV_WSCALE + btop[gw]);
        }
        gsync(++ep);

        // ---- X5: top gates, recon_top = Vmid[3]·h5; fused TD0/BU1/loss0 for t+1 ----
        {
            const bool more = (t + 1 < TT);
            {
                const int k = tid;
                float zi = ldf(&g_z[k]),          zf = ldf(&g_z[HH + k]);
                float zg = ldf(&g_z[2 * HH + k]), zo = ldf(&g_z[3 * HH + k]);
                float c_old = ldf(&g_c[p][4][k]);
                float cn = sigm(zf) * c_old + sigm(zi) * tanhf(zg);
                float hn = sigm(zo) * tanhf(cn);
                __half hnh = __float2half_rn(hn);
                shh[k] = hnh;
                if (blockIdx.x == 0) {
                    stf(&g_c[1 - p][4][k], cn);
                    g_xtop[HH + k] = hnh;
                }
            }
            if (more && tid < CC)
                sxf[tid] = fabsf(x_seq[(t + 1) * CC + tid] - ldf(&g_recon1[tid]));
            __syncthreads();
            if (gw < HH) {
                float a = warp_red(dot16<2048>(&h_Vmid[((size_t)3 * HH + gw) * HH], shh, lane));
                if (lane == 0) stf(&g_reconR[3][gw], a + Vmid_b[3 * HH + gw]);
            } else if (more && gw < 2 * HH) {
                int r = gw - HH;
                float a = warp_red(dot56h(&h_W0[(size_t)r * CC], sxf, lane));
                if (lane == 0) g_xin[0][r] = __float2half_rn(a + W0_b[r]);
            }
            if (more && blockIdx.x == 0) {
                float s = block_sum((tid < CC) ? sxf[tid] : 0.f, sred);
                if (tid == 0) stf(&g_loss_parts[t + 1][0], s);
            }
            gsync(++ep);
        }
    }

    // ---- epilogue: deterministic loss reduction (all parts written by block 0) ----
    if (blockIdx.x == 0) {
        const float* parts = &g_loss_parts[0][0];
        float v = 0.f;
        for (int i = tid; i < TT * 5; i += NTHR) v += ldf(&parts[i]);
        float s = block_sum(v, sred);
        if (tid == 0) out[0] = s;
    }
}

// ---------------- launch ---------------------------------------------------------
extern "C" void kernel_launch(void* const* d_in, const int* in_sizes, int n_in,
                              void* d_out, int out_size) {
    (void)in_sizes; (void)n_in; (void)out_size;
    const float* x_seq  = (const float*)d_in[0];
    const float* W0_w   = (const float*)d_in[1];
    const float* W0_b   = (const float*)d_in[2];
    const float* Wmid_w = (const float*)d_in[3];
    const float* Wmid_b = (const float*)d_in[4];
    const float* V1_w   = (const float*)d_in[5];
    const float* V1_b   = (const float*)d_in[6];
    const float* Vmid_w = (const float*)d_in[7];
    const float* Vmid_b = (const float*)d_in[8];
    const float* Wihm   = (const float*)d_in[9];
    const float* Whhm   = (const float*)d_in[10];
    const float* bmid   = (const float*)d_in[11];
    const float* Wiht   = (const float*)d_in[12];
    const float* Whht   = (const float*)d_in[13];
    const float* btop   = (const float*)d_in[14];

    convert_kernel<<<2048, 256>>>(W0_w, Wmid_w, V1_w, Vmid_w, Wihm, Whhm, Wiht, Whht);
    predcells_kernel<<<NBLK, NTHR>>>(x_seq, W0_b, Wmid_b, V1_b, Vmid_b, bmid, btop,
                                     (float*)d_out);
}

// round 7
// speedup vs baseline: 1.7825x; 1.7825x over previous
#include <cuda_runtime.h>
#include <cuda_fp16.h>
#include <cuda_fp8.h>

#define TT 256
#define CC 56
#define HH 1024
#define NBLK 148
#define NTHR 1024
#define INV_WSCALE (1.0f/64.0f)

// ---------------- folded / quantized weights (built per launch) ----------------
__device__ __align__(16) __half  h_F[4][(size_t)4096*1024];   // F_{m->m+1} fp16
__device__ __align__(16) __half  h_F0[(size_t)4096*64];       // Wih0[:,:H]*W0 (56 cols, stride 64)
__device__ __align__(16) unsigned char w8_G[4][(size_t)4096*2048]; // [Wih[:,H:]|Whh] fp8, mid layers
__device__ __align__(16) unsigned char w8_Gtop[(size_t)4096*1024]; // Whh_top fp8
__device__ __align__(16) __half  h_Vmid[(size_t)4*1024*1024];
__device__ __align__(16) __half  h_V1[(size_t)56*1024];
__device__ float d_gbase[5][4096];     // folded bias constants per layer

// ---------------- runtime state ------------------------------------------------
__device__ float g_z[5][4096];         // z per layer (written one phase earlier)
__device__ float g_G[5][4096];         // background G vectors
__device__ __align__(4) __half g_reconR[4][HH];
__device__ __align__(4) __half g_recon1[64];
__device__ float g_loss_parts[TT][5];
__device__ unsigned g_arrive[NBLK];

// ---------------- helpers ------------------------------------------------------
__device__ __forceinline__ float ldf(const float* p) { return __ldcg(p); }
__device__ __forceinline__ void  stf(float* p, float v) { __stcg(p, v); }
__device__ __forceinline__ float ldh(const __half* p) {
    unsigned short u = __ldcg(reinterpret_cast<const unsigned short*>(p));
    return __half2float(__ushort_as_half(u));
}
__device__ __forceinline__ void sth(__half* p, float v) {
    __stcg(reinterpret_cast<unsigned short*>(p), __half_as_ushort(__float2half_rn(v)));
}

__device__ __forceinline__ float warp_red(float v) {
#pragma unroll
    for (int o = 16; o; o >>= 1) v += __shfl_xor_sync(0xffffffffu, v, o);
    return v;
}

__device__ __forceinline__ __half2 cvt8(unsigned v16) {
    __half2_raw r = __nv_cvt_fp8x2_to_halfraw2((__nv_fp8x2_storage_t)v16, __NV_E4M3);
    return *reinterpret_cast<__half2*>(&r);
}
__device__ __forceinline__ float hsum(__half2 h) {
    float2 f = __half22float2(h);
    return f.x + f.y;
}

template<int NB>
__device__ __forceinline__ float dot8(const unsigned char* __restrict__ w,
                                      const __half* __restrict__ x, int lane) {
    float acc = 0.f;
#pragma unroll
    for (int it = 0; it < NB / 512; it++) {
        int c = it * 512 + lane * 16;
        uint4 wv  = *reinterpret_cast<const uint4*>(w + c);
        uint4 xv0 = *reinterpret_cast<const uint4*>(reinterpret_cast<const char*>(x) + 2 * c);
        uint4 xv1 = *reinterpret_cast<const uint4*>(reinterpret_cast<const char*>(x) + 2 * c + 16);
        const __half2* xa = reinterpret_cast<const __half2*>(&xv0);
        const __half2* xb = reinterpret_cast<const __half2*>(&xv1);
        __half2 s = __floats2half2_rn(0.f, 0.f);
        s = __hfma2(cvt8(wv.x & 0xffffu), xa[0], s);
        s = __hfma2(cvt8(wv.x >> 16),     xa[1], s);
        s = __hfma2(cvt8(wv.y & 0xffffu), xa[2], s);
        s = __hfma2(cvt8(wv.y >> 16),     xa[3], s);
        s = __hfma2(cvt8(wv.z & 0xffffu), xb[0], s);
        s = __hfma2(cvt8(wv.z >> 16),     xb[1], s);
        s = __hfma2(cvt8(wv.w & 0xffffu), xb[2], s);
        s = __hfma2(cvt8(wv.w >> 16),     xb[3], s);
        acc += hsum(s);
    }
    return acc;
}

template<int NB>
__device__ __forceinline__ float dot16(const __half* __restrict__ w,
                                       const __half* __restrict__ x, int lane) {
    float acc = 0.f;
#pragma unroll
    for (int it = 0; it < NB / 512; it++) {
        int c = it * 512 + lane * 16;
        uint4 wv = *reinterpret_cast<const uint4*>(reinterpret_cast<const char*>(w) + c);
        uint4 xv = *reinterpret_cast<const uint4*>(reinterpret_cast<const char*>(x) + c);
        const __half2* wa = reinterpret_cast<const __half2*>(&wv);
        const __half2* xa = reinterpret_cast<const __half2*>(&xv);
        __half2 s = __floats2half2_rn(0.f, 0.f);
        s = __hfma2(wa[0], xa[0], s);
        s = __hfma2(wa[1], xa[1], s);
        s = __hfma2(wa[2], xa[2], s);
        s = __hfma2(wa[3], xa[3], s);
        acc += hsum(s);
    }
    return acc;
}

__device__ __forceinline__ float dot56h(const __half* __restrict__ w,
                                        const float* __restrict__ x, int lane) {
    float acc = 0.f;
    if (lane < 28) {
        __half2 h = *reinterpret_cast<const __half2*>(w + lane * 2);
        float2 f = __half22float2(h);
        acc = f.x * x[lane * 2] + f.y * x[lane * 2 + 1];
    }
    return acc;
}

__device__ __forceinline__ float sigm(float x) { return 1.f / (1.f + __expf(-x)); }

__device__ __forceinline__ void gsync(unsigned ep) {
    __syncthreads();
    if (threadIdx.x < 32) {
        if (threadIdx.x == 0)
            asm volatile("st.release.gpu.global.b32 [%0], %1;"
                         :: "l"(g_arrive + blockIdx.x), "r"(ep) : "memory");
        const int lane = threadIdx.x;
        bool done = false;
        while (!done) {
            bool ok = true;
#pragma unroll
            for (int j = 0; j < 5; j++) {
                int s = lane + j * 32;
                if (s < NBLK) {
                    unsigned v;
                    asm volatile("ld.acquire.gpu.global.b32 %0, [%1];"
                                 : "=r"(v) : "l"(g_arrive + s) : "memory");
                    ok &= ((int)(v - ep) >= 0);
                }
            }
            done = __all_sync(0xffffffffu, ok);
        }
    }
    __syncthreads();
}

__device__ __forceinline__ float block_sum(float v, float* sred) {
    int lane = threadIdx.x & 31, w = threadIdx.x >> 5;
    v = warp_red(v);
    if (lane == 0) sred[w] = v;
    __syncthreads();
    float r = 0.f;
    if (w == 0) {
        r = (lane < NTHR / 32) ? sred[lane] : 0.f;
        r = warp_red(r);
    }
    __syncthreads();
    return r;
}

// Background tasks. 4096 G rows + nv V rows must be covered by 4736 warps:
//   gw >= 4096        -> G row gw-4096           (0..639)
//   gw <  3456        -> G row gw+640            (640..4095)
//   gw in [3456,4096) -> V row gw-3456           (0..639)
//   gw in [3456,3840) -> V row gw-3456+640       (640..1023, second task)
__device__ __forceinline__ void bg_work(int gw, int lane,
                                        const unsigned char* __restrict__ gwts, int gbytes,
                                        const __half* __restrict__ gin,
                                        float* __restrict__ gout,
                                        const float* __restrict__ gbase,
                                        int nv,
                                        const __half* __restrict__ vwts,
                                        const __half* __restrict__ vin,
                                        __half* __restrict__ vout,
                                        const float* __restrict__ vbias) {
    if (gw >= 4096 || gw < 3456) {
        int r = (gw >= 4096) ? (gw - 4096) : (gw + 640);
        float a = (gbytes == 2048) ? dot8<2048>(gwts + (size_t)r * 2048, gin, lane)
                                   : dot8<1024>(gwts + (size_t)r * 1024, gin, lane);
        a = warp_red(a);
        if (lane == 0) stf(&gout[r], a * INV_WSCALE + gbase[r]);
    } else {
        int v = gw - 3456;
        if (v < nv) {
            float a = warp_red(dot16<2048>(vwts + (size_t)v * 1024, vin, lane));
            if (lane == 0) sth(&vout[v], a + vbias[v]);
        }
        int v2 = v + 640;
        if (v < 384 && v2 < nv) {
            float a = warp_red(dot16<2048>(vwts + (size_t)v2 * 1024, vin, lane));
            if (lane == 0) sth(&vout[v2], a + vbias[v2]);
        }
    }
}

// ---------------- pre-pass 1: fold GEMMs F = Wih[:,:H] x Wmid -------------------
__global__ void gemm_fold(const float* __restrict__ Wihm,
                          const float* __restrict__ Wiht,
                          const float* __restrict__ Wmid) {
    __shared__ float As[16][128];
    __shared__ float Bs[16][128];
    const int z = blockIdx.z;
    const float* A = (z < 3) ? (Wihm + (size_t)(z + 1) * 4096 * 2048) : Wiht;
    const int lda = (z < 3) ? 2048 : 1024;
    const float* B = Wmid + (size_t)z * 1024 * 1024;
    __half* C = &h_F[z][0];
    const int m0 = blockIdx.y * 128;
    const int n0 = blockIdx.x * 128;
    const int tid = threadIdx.x;
    const int ty = tid / 16, tx = tid % 16;
    float acc[8][8] = {};
    for (int k0 = 0; k0 < 1024; k0 += 16) {
#pragma unroll
        for (int i = 0; i < 2; i++) {
            int s = tid + i * 256;
            int row = s >> 2;
            int cc = (s & 3) * 4;
            float4 v = *reinterpret_cast<const float4*>(A + (size_t)(m0 + row) * lda + k0 + cc);
            As[cc + 0][row] = v.x; As[cc + 1][row] = v.y;
            As[cc + 2][row] = v.z; As[cc + 3][row] = v.w;
        }
#pragma unroll
        for (int i = 0; i < 2; i++) {
            int s = tid + i * 256;
            int row = s >> 5;
            int cc = (s & 31) * 4;
            *reinterpret_cast<float4*>(&Bs[row][cc]) =
                *reinterpret_cast<const float4*>(B + (size_t)(k0 + row) * 1024 + n0 + cc);
        }
        __syncthreads();
#pragma unroll
        for (int k = 0; k < 16; k++) {
            float a[8], b[8];
            *reinterpret_cast<float4*>(a)     = *reinterpret_cast<float4*>(&As[k][ty * 8]);
            *reinterpret_cast<float4*>(a + 4) = *reinterpret_cast<float4*>(&As[k][ty * 8 + 4]);
            *reinterpret_cast<float4*>(b)     = *reinterpret_cast<float4*>(&Bs[k][tx * 8]);
            *reinterpret_cast<float4*>(b + 4) = *reinterpret_cast<float4*>(&Bs[k][tx * 8 + 4]);
#pragma unroll
            for (int i = 0; i < 8; i++)
#pragma unroll
                for (int j = 0; j < 8; j++)
                    acc[i][j] = fmaf(a[i], b[j], acc[i][j]);
        }
        __syncthreads();
    }
#pragma unroll
    for (int i = 0; i < 8; i++)
#pragma unroll
        for (int j = 0; j < 8; j++)
            C[(size_t)(m0 + ty * 8 + i) * 1024 + n0 + tx * 8 + j] = __float2half_rn(acc[i][j]);
}

// ---------------- pre-pass 2: F0 = Wih0[:,:H] x W0 ------------------------------
__global__ void f0_fold(const float* __restrict__ Wihm, const float* __restrict__ W0w) {
    int wid = threadIdx.x >> 5, lane = threadIdx.x & 31;
    int r = blockIdx.x * 8 + wid;
    float a[32];
    const float* Arow = Wihm + (size_t)r * 2048;
#pragma unroll
    for (int j = 0; j < 32; j++) a[j] = Arow[lane + 32 * j];
    for (int c = 0; c < CC; c++) {
        float s = 0.f;
#pragma unroll
        for (int j = 0; j < 32; j++) s = fmaf(a[j], W0w[(lane + 32 * j) * CC + c], s);
        s = warp_red(s);
        if (lane == 0) h_F0[(size_t)r * 64 + c] = __float2half_rn(s);
    }
}

// ---------------- pre-pass 3: folded bias constants ------------------------------
__global__ void gbase_kernel(const float* __restrict__ Wihm, const float* __restrict__ Wiht,
                             const float* __restrict__ W0_b, const float* __restrict__ Wmid_b,
                             const float* __restrict__ bmid, const float* __restrict__ btop) {
    int gwarp = (blockIdx.x * blockDim.x + threadIdx.x) >> 5;
    int lane = threadIdx.x & 31;
    if (gwarp >= 5 * 4096) return;
    int lay = gwarp >> 12;
    int r = gwarp & 4095;
    const float* Arow;
    const float* bv;
    float bias;
    if (lay < 4) {
        Arow = Wihm + ((size_t)lay * 4096 + r) * 2048;
        bv = (lay == 0) ? W0_b : (Wmid_b + (lay - 1) * 1024);
        bias = bmid[lay * 4096 + r];
    } else {
        Arow = Wiht + (size_t)r * 1024;
        bv = Wmid_b + 3 * 1024;
        bias = btop[r];
    }
    float s = 0.f;
    for (int j = lane; j < 1024; j += 32) s = fmaf(Arow[j], bv[j], s);
    s = warp_red(s);
    if (lane == 0) d_gbase[lay][r] = s + bias;
}

// ---------------- pre-pass 4: quantize/pack runtime weights ---------------------
__global__ void convert_kernel(const float* __restrict__ V1, const float* __restrict__ Vmid,
                               const float* __restrict__ Wihm, const float* __restrict__ Whhm,
                               const float* __restrict__ Whht) {
    long i0 = (long)blockIdx.x * blockDim.x + threadIdx.x;
    long st = (long)gridDim.x * blockDim.x;
#define PACK8(v) ( (unsigned)__nv_cvt_float2_to_fp8x2(make_float2((v).x*64.f,(v).y*64.f), __NV_SATFINITE, __NV_E4M3) \
                 | ((unsigned)__nv_cvt_float2_to_fp8x2(make_float2((v).z*64.f,(v).w*64.f), __NV_SATFINITE, __NV_E4M3) << 16) )
    // G part 1: Wih second half -> bytes [0,1024) of each 2048B row
    for (long i = i0; i < 16384L * 256; i += st) {
        long row = i >> 8; int jj = (int)(i & 255) * 4;
        float4 v = *reinterpret_cast<const float4*>(Wihm + row * 2048 + 1024 + jj);
        reinterpret_cast<unsigned*>(&w8_G[0][0])[row * 512 + (jj >> 2)] = PACK8(v);
    }
    // G part 2: Whh -> bytes [1024,2048)
    for (long i = i0; i < 16384L * 256; i += st) {
        long row = i >> 8; int jj = (int)(i & 255) * 4;
        float4 v = *reinterpret_cast<const float4*>(Whhm + row * 1024 + jj);
        reinterpret_cast<unsigned*>(&w8_G[0][0])[row * 512 + 256 + (jj >> 2)] = PACK8(v);
    }
    // top Whh
    for (long i = i0; i < 4096L * 256; i += st) {
        float4 v = *reinterpret_cast<const float4*>(Whht + i * 4);
        reinterpret_cast<unsigned*>(w8_Gtop)[i] = PACK8(v);
    }
#undef PACK8
    for (long i = i0; i < 4L * 1024 * 1024 / 2; i += st)
        reinterpret_cast<__half2*>(h_Vmid)[i] = __float22half2_rn(reinterpret_cast<const float2*>(Vmid)[i]);
    for (long i = i0; i < 56L * 1024 / 2; i += st)
        reinterpret_cast<__half2*>(h_V1)[i] = __float22half2_rn(reinterpret_cast<const float2*>(V1)[i]);
}

// ---------------- main persistent kernel ----------------------------------------
__global__ void __launch_bounds__(NTHR, 1)
predcells_kernel(const float* __restrict__ x_seq,
                 const float* __restrict__ V1_b, const float* __restrict__ Vmid_b,
                 float* __restrict__ out) {
    __shared__ __align__(16) __half sbuf[2][2048];   // ping-pong [TD(1024)|h(1024)]
    __shared__ float sTD0[64];
    __shared__ float sred[32];

    const int tid  = threadIdx.x;
    const int lane = tid & 31;
    const int wid  = tid >> 5;
    const int gw   = blockIdx.x * (NTHR / 32) + wid;
    const long gtid = (long)blockIdx.x * NTHR + tid;
    const long gsz  = (long)NBLK * NTHR;

    float c_reg[5] = {0.f, 0.f, 0.f, 0.f, 0.f};
    unsigned ep = g_arrive[blockIdx.x];

    // ---- prologue A: init state ----
    {   // zero both smem ping-pong buffers
        __half* sb = &sbuf[0][0];
        for (int i = tid; i < 4096; i += NTHR) sb[i] = __ushort_as_half(0);
    }
    for (long i = gtid; i < 4 * HH; i += gsz) (&g_reconR[0][0])[i] = __ushort_as_half(0);
    for (long i = gtid; i < 64; i += gsz) g_recon1[i] = __ushort_as_half(0);
    for (long i = gtid; i < 5 * 4096; i += gsz) (&g_G[0][0])[i] = (&d_gbase[0][0])[i];
    float td0p = 0.f;
    if (tid < CC) { td0p = fabsf(x_seq[tid]); sTD0[tid] = td0p; }
    __syncthreads();
    gsync(++ep);

    // ---- prologue B: z_0(0) = F0*|x_0| + G_0 ----
    if (gw < 4096) {
        float a = warp_red(dot56h(&h_F0[(size_t)gw * 64], sTD0, lane));
        if (lane == 0) stf(&g_z[0][gw], a + ldf(&g_G[0][gw]));
    }
    if (blockIdx.x == 0) {
        float s = block_sum(td0p, sred);
        if (tid == 0) stf(&g_loss_parts[0][0], s);
    }
    gsync(++ep);

    int pp = 0;
    for (int t = 0; t < TT; t++) {
        // ---- phases 0..3: mid layers ----
#pragma unroll 1
        for (int ph = 0; ph < 4; ph++) {
            __half* cur = &sbuf[pp][0];
            const __half* prv = &sbuf[pp ^ 1][0];
            // gates (redundant per block), register-resident c
            float td;
            {
                const int k = tid;
                float zi = ldf(&g_z[ph][k]);
                float zf = ldf(&g_z[ph][1024 + k]);
                float zg = ldf(&g_z[ph][2048 + k]);
                float zo = ldf(&g_z[ph][3072 + k]);
                float cn = sigm(zf) * c_reg[ph] + sigm(zi) * tanhf(zg);
                c_reg[ph] = cn;
                float hn = sigm(zo) * tanhf(cn);
                td = fabsf(hn - ldh(&g_reconR[ph][k]));
                cur[k] = __float2half_rn(td);
                cur[1024 + k] = __float2half_rn(hn);
            }
            __syncthreads();
            // chain: z_{ph+1} = F_ph * TD + G_{ph+1}
            if (gw < 4096) {
                float a = warp_red(dot16<2048>(&h_F[ph][(size_t)gw * 1024], cur, lane));
                if (lane == 0) stf(&g_z[ph + 1][gw], a + ldf(&g_G[ph + 1][gw]));
            }
            // background
            switch (ph) {
            case 0: bg_work(gw, lane, w8_Gtop, 1024, prv + 1024, g_G[4], d_gbase[4],
                            (t > 0) ? 1024 : 0, h_Vmid + (size_t)3 * 1024 * 1024, prv + 1024,
                            g_reconR[3], Vmid_b + 3072); break;
            case 1: bg_work(gw, lane, &w8_G[0][0], 2048, prv, g_G[0], d_gbase[0],
                            56, h_V1, prv + 1024, g_recon1, V1_b); break;
            case 2: bg_work(gw, lane, &w8_G[1][0], 2048, prv, g_G[1], d_gbase[1],
                            1024, h_Vmid, prv + 1024, g_reconR[0], Vmid_b); break;
            case 3: bg_work(gw, lane, &w8_G[2][0], 2048, prv, g_G[2], d_gbase[2],
                            1024, h_Vmid + (size_t)1024 * 1024, prv + 1024,
                            g_reconR[1], Vmid_b + 1024); break;
            }
            if (blockIdx.x == 0) {
                float s = block_sum(td, sred);
                if (tid == 0) stf(&g_loss_parts[t][1 + ph], s);
            }
            gsync(++ep);
            pp ^= 1;
        }

        // ---- phase 4: top gates + z_0(t+1) ----
        {
            const bool more = (t + 1 < TT);
            __half* cur = &sbuf[pp][0];
            const __half* prv = &sbuf[pp ^ 1][0];
            {
                const int k = tid;
                float zi = ldf(&g_z[4][k]);
                float zf = ldf(&g_z[4][1024 + k]);
                float zg = ldf(&g_z[4][2048 + k]);
                float zo = ldf(&g_z[4][3072 + k]);
                float cn = sigm(zf) * c_reg[4] + sigm(zi) * tanhf(zg);
                c_reg[4] = cn;
                cur[1024 + k] = __float2half_rn(sigm(zo) * tanhf(cn));
            }
            float td0 = 0.f;
            if (more && tid < CC) {
                td0 = fabsf(x_seq[(t + 1) * CC + tid] - ldh(&g_recon1[tid]));
                sTD0[tid] = td0;
            }
            __syncthreads();
            if (more && gw < 4096) {
                float a = warp_red(dot56h(&h_F0[(size_t)gw * 64], sTD0, lane));
                if (lane == 0) stf(&g_z[0][gw], a + ldf(&g_G[0][gw]));
            }
            bg_work(gw, lane, &w8_G[3][0], 2048, prv, g_G[3], d_gbase[3],
                    1024, h_Vmid + (size_t)2 * 1024 * 1024, prv + 1024,
                    g_reconR[2], Vmid_b + 2048);
            if (more && blockIdx.x == 0) {
                float s = block_sum(td0, sred);
                if (tid == 0) stf(&g_loss_parts[t + 1][0], s);
            }
            gsync(++ep);
            pp ^= 1;
        }
    }

    // ---- epilogue: deterministic loss reduction ----
    if (blockIdx.x == 0) {
        const float* parts = &g_loss_parts[0][0];
        float v = 0.f;
        for (int i = tid; i < TT * 5; i += NTHR) v += ldf(&parts[i]);
        float s = block_sum(v, sred);
        if (tid == 0) out[0] = s;
    }
}

// ---------------- launch ---------------------------------------------------------
extern "C" void kernel_launch(void* const* d_in, const int* in_sizes, int n_in,
                              void* d_out, int out_size) {
    (void)in_sizes; (void)n_in; (void)out_size;
    const float* x_seq  = (const float*)d_in[0];
    const float* W0_w   = (const float*)d_in[1];
    const float* W0_b   = (const float*)d_in[2];
    const float* Wmid_w = (const float*)d_in[3];
    const float* Wmid_b = (const float*)d_in[4];
    const float* V1_w   = (const float*)d_in[5];
    const float* V1_b   = (const float*)d_in[6];
    const float* Vmid_w = (const float*)d_in[7];
    const float* Vmid_b = (const float*)d_in[8];
    const float* Wihm   = (const float*)d_in[9];
    const float* Whhm   = (const float*)d_in[10];
    const float* bmid   = (const float*)d_in[11];
    const float* Wiht   = (const float*)d_in[12];
    const float* Whht   = (const float*)d_in[13];
    const float* btop   = (const float*)d_in[14];

    gemm_fold<<<dim3(8, 32, 4), 256>>>(Wihm, Wiht, Wmid_w);
    f0_fold<<<512, 256>>>(Wihm, W0_w);
    gbase_kernel<<<2560, 256>>>(Wihm, Wiht, W0_b, Wmid_b, bmid, btop);
    convert_kernel<<<2048, 256>>>(V1_w, Vmid_w, Wihm, Whhm, Whht);
    predcells_kernel<<<NBLK, NTHR>>>(x_seq, V1_b, Vmid_b, (float*)d_out);
}

// round 8
// speedup vs baseline: 2.3672x; 1.3280x over previous
#include <cuda_runtime.h>
#include <cuda_fp16.h>
#include <cuda_fp8.h>

#define TT 256
#define CC 56
#define HH 1024
#define NBLK 148
#define NTHR 1024
#define INV_WSCALE (1.0f/64.0f)

// ---------------- folded / quantized weights (built per launch) ----------------
__device__ __align__(16) __half  h_F[4][(size_t)4096*1024];   // F_{m->m+1} fp16
__device__ __align__(16) __half  h_F0[(size_t)4096*64];       // Wih0[:,:H]*W0 (56 cols, stride 64)
__device__ __align__(16) unsigned char w8_G[4][(size_t)4096*2048]; // [Wih[:,H:]|Whh] fp8
__device__ __align__(16) unsigned char w8_Gtop[(size_t)4096*1024]; // Whh_top fp8
__device__ __align__(16) __half  h_Vmid[(size_t)4*1024*1024];
__device__ __align__(16) __half  h_V1[(size_t)56*1024];
__device__ float d_gbase[5][4096];

// fp16 staging for the tensor-core fold GEMM
__device__ __align__(16) __half  h_A16[(size_t)4*4096*1024];  // Wih_{z+1}[:, :H] (z<3), Wiht (z=3)
__device__ __align__(16) __half  h_BT[(size_t)4*1024*1024];   // Wmid^T (col-major B)

// ---------------- runtime state ------------------------------------------------
__device__ float g_z[5][4096];
__device__ float g_G[5][4096];
__device__ __align__(4) __half g_reconR[4][HH];
__device__ __align__(4) __half g_recon1[64];
__device__ float g_loss_parts[TT][5];
__device__ unsigned g_arrive[NBLK];

// ---------------- helpers ------------------------------------------------------
__device__ __forceinline__ float ldf(const float* p) { return __ldcg(p); }
__device__ __forceinline__ void  stf(float* p, float v) { __stcg(p, v); }
__device__ __forceinline__ float ldh(const __half* p) {
    unsigned short u = __ldcg(reinterpret_cast<const unsigned short*>(p));
    return __half2float(__ushort_as_half(u));
}
__device__ __forceinline__ void sth(__half* p, float v) {
    __stcg(reinterpret_cast<unsigned short*>(p), __half_as_ushort(__float2half_rn(v)));
}

__device__ __forceinline__ float warp_red(float v) {
#pragma unroll
    for (int o = 16; o; o >>= 1) v += __shfl_xor_sync(0xffffffffu, v, o);
    return v;
}

__device__ __forceinline__ __half2 cvt8(unsigned v16) {
    __half2_raw r = __nv_cvt_fp8x2_to_halfraw2((__nv_fp8x2_storage_t)v16, __NV_E4M3);
    return *reinterpret_cast<__half2*>(&r);
}
__device__ __forceinline__ float hsum(__half2 h) {
    float2 f = __half22float2(h);
    return f.x + f.y;
}

template<int NB>
__device__ __forceinline__ float dot8(const unsigned char* __restrict__ w,
                                      const __half* __restrict__ x, int lane) {
    float acc = 0.f;
#pragma unroll
    for (int it = 0; it < NB / 512; it++) {
        int c = it * 512 + lane * 16;
        uint4 wv  = *reinterpret_cast<const uint4*>(w + c);
        uint4 xv0 = *reinterpret_cast<const uint4*>(reinterpret_cast<const char*>(x) + 2 * c);
        uint4 xv1 = *reinterpret_cast<const uint4*>(reinterpret_cast<const char*>(x) + 2 * c + 16);
        const __half2* xa = reinterpret_cast<const __half2*>(&xv0);
        const __half2* xb = reinterpret_cast<const __half2*>(&xv1);
        __half2 s = __floats2half2_rn(0.f, 0.f);
        s = __hfma2(cvt8(wv.x & 0xffffu), xa[0], s);
        s = __hfma2(cvt8(wv.x >> 16),     xa[1], s);
        s = __hfma2(cvt8(wv.y & 0xffffu), xa[2], s);
        s = __hfma2(cvt8(wv.y >> 16),     xa[3], s);
        s = __hfma2(cvt8(wv.z & 0xffffu), xb[0], s);
        s = __hfma2(cvt8(wv.z >> 16),     xb[1], s);
        s = __hfma2(cvt8(wv.w & 0xffffu), xb[2], s);
        s = __hfma2(cvt8(wv.w >> 16),     xb[3], s);
        acc += hsum(s);
    }
    return acc;
}

template<int NB>
__device__ __forceinline__ float dot16(const __half* __restrict__ w,
                                       const __half* __restrict__ x, int lane) {
    float acc = 0.f;
#pragma unroll
    for (int it = 0; it < NB / 512; it++) {
        int c = it * 512 + lane * 16;
        uint4 wv = *reinterpret_cast<const uint4*>(reinterpret_cast<const char*>(w) + c);
        uint4 xv = *reinterpret_cast<const uint4*>(reinterpret_cast<const char*>(x) + c);
        const __half2* wa = reinterpret_cast<const __half2*>(&wv);
        const __half2* xa = reinterpret_cast<const __half2*>(&xv);
        __half2 s = __floats2half2_rn(0.f, 0.f);
        s = __hfma2(wa[0], xa[0], s);
        s = __hfma2(wa[1], xa[1], s);
        s = __hfma2(wa[2], xa[2], s);
        s = __hfma2(wa[3], xa[3], s);
        acc += hsum(s);
    }
    return acc;
}

__device__ __forceinline__ float dot56h(const __half* __restrict__ w,
                                        const float* __restrict__ x, int lane) {
    float acc = 0.f;
    if (lane < 28) {
        __half2 h = *reinterpret_cast<const __half2*>(w + lane * 2);
        float2 f = __half22float2(h);
        acc = f.x * x[lane * 2] + f.y * x[lane * 2 + 1];
    }
    return acc;
}

__device__ __forceinline__ float sigm(float x) { return 1.f / (1.f + __expf(-x)); }

// ---- split grid barrier: arrive (release) / wait (acquire) --------------------
__device__ __forceinline__ void bar_arrive(unsigned ep) {
    __syncthreads();
    if (threadIdx.x == 0)
        asm volatile("st.release.gpu.global.b32 [%0], %1;"
                     :: "l"(g_arrive + blockIdx.x), "r"(ep) : "memory");
}
__device__ __forceinline__ void bar_wait(unsigned ep) {
    if (threadIdx.x < 32) {
        const int lane = threadIdx.x;
        bool done = false;
        while (!done) {
            bool ok = true;
#pragma unroll
            for (int j = 0; j < 5; j++) {
                int s = lane + j * 32;
                if (s < NBLK) {
                    unsigned v;
                    asm volatile("ld.acquire.gpu.global.b32 %0, [%1];"
                                 : "=r"(v) : "l"(g_arrive + s) : "memory");
                    ok &= ((int)(v - ep) >= 0);
                }
            }
            done = __all_sync(0xffffffffu, ok);
        }
    }
    __syncthreads();
}

__device__ __forceinline__ float block_sum(float v, float* sred) {
    int lane = threadIdx.x & 31, w = threadIdx.x >> 5;
    v = warp_red(v);
    if (lane == 0) sred[w] = v;
    __syncthreads();
    float r = 0.f;
    if (w == 0) {
        r = (lane < NTHR / 32) ? sred[lane] : 0.f;
        r = warp_red(r);
    }
    __syncthreads();
    return r;
}

// Background tasks: 4096 G rows + nv V rows over 4736 warps (see round-7 map).
__device__ __forceinline__ void bg_work(int gw, int lane,
                                        const unsigned char* __restrict__ gwts, int gbytes,
                                        const __half* __restrict__ gin,
                                        float* __restrict__ gout,
                                        const float* __restrict__ gbase,
                                        int nv,
                                        const __half* __restrict__ vwts,
                                        const __half* __restrict__ vin,
                                        __half* __restrict__ vout,
                                        const float* __restrict__ vbias) {
    if (gw >= 4096 || gw < 3456) {
        int r = (gw >= 4096) ? (gw - 4096) : (gw + 640);
        float a = (gbytes == 2048) ? dot8<2048>(gwts + (size_t)r * 2048, gin, lane)
                                   : dot8<1024>(gwts + (size_t)r * 1024, gin, lane);
        a = warp_red(a);
        if (lane == 0) stf(&gout[r], a * INV_WSCALE + gbase[r]);
    } else {
        int v = gw - 3456;
        if (v < nv) {
            float a = warp_red(dot16<2048>(vwts + (size_t)v * 1024, vin, lane));
            if (lane == 0) sth(&vout[v], a + vbias[v]);
        }
        int v2 = v + 640;
        if (v < 384 && v2 < nv) {
            float a = warp_red(dot16<2048>(vwts + (size_t)v2 * 1024, vin, lane));
            if (lane == 0) sth(&vout[v2], a + vbias[v2]);
        }
    }
}

// ---------------- pre-pass 0: fp16 staging for the fold GEMM --------------------
__global__ void conv_ab(const float* __restrict__ Wihm, const float* __restrict__ Wiht,
                        const float* __restrict__ Wmid) {
    long i0 = (long)blockIdx.x * blockDim.x + threadIdx.x;
    long st = (long)gridDim.x * blockDim.x;
    // A16[z][r][0:1024] = fp16 of Wih_{z+1}[r][0:1024] (z<3) or Wiht[r][:]
    for (long i = i0; i < 4L * 4096 * 256; i += st) {
        long zr = i >> 8;
        int z = (int)(zr >> 12);
        long r = zr & 4095;
        int cc = (int)(i & 255) * 4;
        const float* src = (z < 3) ? (Wihm + ((size_t)(z + 1) * 4096 + r) * 2048 + cc)
                                   : (Wiht + (size_t)r * 1024 + cc);
        float4 v = *reinterpret_cast<const float4*>(src);
        *reinterpret_cast<__half2*>(h_A16 + zr * 1024 + cc)     = __floats2half2_rn(v.x, v.y);
        *reinterpret_cast<__half2*>(h_A16 + zr * 1024 + cc + 2) = __floats2half2_rn(v.z, v.w);
    }
    // BT[z][j][i] = Wmid[z][i][j]
    for (long i = i0; i < 4L * 1024 * 1024; i += st) {
        long z = i >> 20;
        int ii = (int)((i >> 10) & 1023);
        int j  = (int)(i & 1023);
        h_BT[z * 1048576 + (size_t)j * 1024 + ii] =
            __float2half_rn(Wmid[z * 1048576 + (size_t)ii * 1024 + j]);
    }
}

// ---------------- pre-pass 1: fold GEMM via mma.sync (HMMA) ---------------------
// F[z] = A16[z] (4096x1024 row) x B (1024x1024, col-major as BT), fp32 accum.
__global__ void gemm_fold_mma() {
    const int z = blockIdx.z;
    const __half* A  = h_A16 + (size_t)z * 4096 * 1024;
    const __half* BT = h_BT  + (size_t)z * 1024 * 1024;
    __half* C = &h_F[z][0];
    const int wid = threadIdx.x >> 5, lane = threadIdx.x & 31;
    const int wm = wid >> 1, wn = wid & 1;
    const int m0 = blockIdx.y * 128 + wm * 32;
    const int n0 = blockIdx.x * 64 + wn * 32;
    const int ra = lane >> 2, kc = (lane & 3) * 2;
    float d[2][4][4] = {};
    for (int k0 = 0; k0 < 1024; k0 += 16) {
        unsigned a[2][4], b[4][2];
#pragma unroll
        for (int t = 0; t < 2; t++) {
            const __half* Ab = A + (size_t)(m0 + t * 16 + ra) * 1024 + k0 + kc;
            a[t][0] = *reinterpret_cast<const unsigned*>(Ab);
            a[t][1] = *reinterpret_cast<const unsigned*>(Ab + 8 * 1024);
            a[t][2] = *reinterpret_cast<const unsigned*>(Ab + 8);
            a[t][3] = *reinterpret_cast<const unsigned*>(Ab + 8 * 1024 + 8);
        }
#pragma unroll
        for (int u = 0; u < 4; u++) {
            const __half* Bb = BT + (size_t)(n0 + u * 8 + ra) * 1024 + k0 + kc;
            b[u][0] = *reinterpret_cast<const unsigned*>(Bb);
            b[u][1] = *reinterpret_cast<const unsigned*>(Bb + 8);
        }
#pragma unroll
        for (int t = 0; t < 2; t++)
#pragma unroll
            for (int u = 0; u < 4; u++)
                asm volatile(
                    "mma.sync.aligned.m16n8k16.row.col.f32.f16.f16.f32 "
                    "{%0,%1,%2,%3}, {%4,%5,%6,%7}, {%8,%9}, {%0,%1,%2,%3};"
                    : "+f"(d[t][u][0]), "+f"(d[t][u][1]), "+f"(d[t][u][2]), "+f"(d[t][u][3])
                    : "r"(a[t][0]), "r"(a[t][1]), "r"(a[t][2]), "r"(a[t][3]),
                      "r"(b[u][0]), "r"(b[u][1]));
    }
#pragma unroll
    for (int t = 0; t < 2; t++)
#pragma unroll
        for (int u = 0; u < 4; u++) {
            int r = m0 + t * 16 + ra, c = n0 + u * 8 + kc;
            *reinterpret_cast<__half2*>(C + (size_t)r * 1024 + c) =
                __floats2half2_rn(d[t][u][0], d[t][u][1]);
            *reinterpret_cast<__half2*>(C + (size_t)(r + 8) * 1024 + c) =
                __floats2half2_rn(d[t][u][2], d[t][u][3]);
        }
}

// ---------------- pre-pass 2: F0 = Wih0[:,:H] x W0 ------------------------------
__global__ void f0_fold(const float* __restrict__ Wihm, const float* __restrict__ W0w) {
    int wid = threadIdx.x >> 5, lane = threadIdx.x & 31;
    int r = blockIdx.x * 8 + wid;
    float a[32];
    const float* Arow = Wihm + (size_t)r * 2048;
#pragma unroll
    for (int j = 0; j < 32; j++) a[j] = Arow[lane + 32 * j];
    for (int c = 0; c < CC; c++) {
        float s = 0.f;
#pragma unroll
        for (int j = 0; j < 32; j++) s = fmaf(a[j], W0w[(lane + 32 * j) * CC + c], s);
        s = warp_red(s);
        if (lane == 0) h_F0[(size_t)r * 64 + c] = __float2half_rn(s);
    }
}

// ---------------- pre-pass 3: folded bias constants ------------------------------
__global__ void gbase_kernel(const float* __restrict__ Wihm, const float* __restrict__ Wiht,
                             const float* __restrict__ W0_b, const float* __restrict__ Wmid_b,
                             const float* __restrict__ bmid, const float* __restrict__ btop) {
    int gwarp = (blockIdx.x * blockDim.x + threadIdx.x) >> 5;
    int lane = threadIdx.x & 31;
    if (gwarp >= 5 * 4096) return;
    int lay = gwarp >> 12;
    int r = gwarp & 4095;
    const float* Arow;
    const float* bv;
    float bias;
    if (lay < 4) {
        Arow = Wihm + ((size_t)lay * 4096 + r) * 2048;
        bv = (lay == 0) ? W0_b : (Wmid_b + (lay - 1) * 1024);
        bias = bmid[lay * 4096 + r];
    } else {
        Arow = Wiht + (size_t)r * 1024;
        bv = Wmid_b + 3 * 1024;
        bias = btop[r];
    }
    float s = 0.f;
    for (int j = lane; j < 1024; j += 32) s = fmaf(Arow[j], bv[j], s);
    s = warp_red(s);
    if (lane == 0) d_gbase[lay][r] = s + bias;
}

// ---------------- pre-pass 4: quantize/pack runtime weights ---------------------
__global__ void convert_kernel(const float* __restrict__ V1, const float* __restrict__ Vmid,
                               const float* __restrict__ Wihm, const float* __restrict__ Whhm,
                               const float* __restrict__ Whht) {
    long i0 = (long)blockIdx.x * blockDim.x + threadIdx.x;
    long st = (long)gridDim.x * blockDim.x;
#define PACK8(v) ( (unsigned)__nv_cvt_float2_to_fp8x2(make_float2((v).x*64.f,(v).y*64.f), __NV_SATFINITE, __NV_E4M3) \
                 | ((unsigned)__nv_cvt_float2_to_fp8x2(make_float2((v).z*64.f,(v).w*64.f), __NV_SATFINITE, __NV_E4M3) << 16) )
    for (long i = i0; i < 16384L * 256; i += st) {
        long row = i >> 8; int jj = (int)(i & 255) * 4;
        float4 v = *reinterpret_cast<const float4*>(Wihm + row * 2048 + 1024 + jj);
        reinterpret_cast<unsigned*>(&w8_G[0][0])[row * 512 + (jj >> 2)] = PACK8(v);
    }
    for (long i = i0; i < 16384L * 256; i += st) {
        long row = i >> 8; int jj = (int)(i & 255) * 4;
        float4 v = *reinterpret_cast<const float4*>(Whhm + row * 1024 + jj);
        reinterpret_cast<unsigned*>(&w8_G[0][0])[row * 512 + 256 + (jj >> 2)] = PACK8(v);
    }
    for (long i = i0; i < 4096L * 256; i += st) {
        float4 v = *reinterpret_cast<const float4*>(Whht + i * 4);
        reinterpret_cast<unsigned*>(w8_Gtop)[i] = PACK8(v);
    }
#undef PACK8
    for (long i = i0; i < 4L * 1024 * 1024 / 2; i += st)
        reinterpret_cast<__half2*>(h_Vmid)[i] = __float22half2_rn(reinterpret_cast<const float2*>(Vmid)[i]);
    for (long i = i0; i < 56L * 1024 / 2; i += st)
        reinterpret_cast<__half2*>(h_V1)[i] = __float22half2_rn(reinterpret_cast<const float2*>(V1)[i]);
}

// ---------------- main persistent kernel ----------------------------------------
__global__ void __launch_bounds__(NTHR, 1)
predcells_kernel(const float* __restrict__ x_seq,
                 const float* __restrict__ V1_b, const float* __restrict__ Vmid_b,
                 float* __restrict__ out) {
    __shared__ __align__(16) __half sbuf[2][2048];   // ping-pong [TD(1024)|h(1024)]
    __shared__ float sTD0[64];
    __shared__ float sred[32];

    const int tid  = threadIdx.x;
    const int lane = tid & 31;
    const int wid  = tid >> 5;
    const int gw   = blockIdx.x * (NTHR / 32) + wid;
    const long gtid = (long)blockIdx.x * NTHR + tid;
    const long gsz  = (long)NBLK * NTHR;

    float c_reg[5] = {0.f, 0.f, 0.f, 0.f, 0.f};
    unsigned ep = g_arrive[blockIdx.x];

    // ---- prologue A: init state ----
    {
        __half* sb = &sbuf[0][0];
        for (int i = tid; i < 4096; i += NTHR) sb[i] = __ushort_as_half(0);
    }
    for (long i = gtid; i < 4 * HH; i += gsz) (&g_reconR[0][0])[i] = __ushort_as_half(0);
    for (long i = gtid; i < 64; i += gsz) g_recon1[i] = __ushort_as_half(0);
    for (long i = gtid; i < 5 * 4096; i += gsz) (&g_G[0][0])[i] = (&d_gbase[0][0])[i];
    float td0p = 0.f;
    if (tid < CC) { td0p = fabsf(x_seq[tid]); sTD0[tid] = td0p; }
    bar_arrive(++ep);
    bar_wait(ep);

    // ---- prologue B: z_0(0) = F0*|x_0| + G_0 ----
    if (gw < 4096) {
        float a = warp_red(dot56h(&h_F0[(size_t)gw * 64], sTD0, lane));
        if (lane == 0) stf(&g_z[0][gw], a + ldf(&g_G[0][gw]));
    }
    bar_arrive(++ep);
    if (blockIdx.x == 0) {
        float s = block_sum(td0p, sred);
        if (tid == 0) stf(&g_loss_parts[0][0], s);
    }
    bar_wait(ep);

    int pp = 0;
    for (int t = 0; t < TT; t++) {
        // ---- phases 0..3: mid layers ----
#pragma unroll 1
        for (int ph = 0; ph < 4; ph++) {
            __half* cur = &sbuf[pp][0];
            const __half* prv = &sbuf[pp ^ 1][0];
            float td;
            {
                const int k = tid;
                float zi = ldf(&g_z[ph][k]);
                float zf = ldf(&g_z[ph][1024 + k]);
                float zg = ldf(&g_z[ph][2048 + k]);
                float zo = ldf(&g_z[ph][3072 + k]);
                float cn = sigm(zf) * c_reg[ph] + sigm(zi) * tanhf(zg);
                c_reg[ph] = cn;
                float hn = sigm(zo) * tanhf(cn);
                td = fabsf(hn - ldh(&g_reconR[ph][k]));
                cur[k] = __float2half_rn(td);
                cur[1024 + k] = __float2half_rn(hn);
            }
            __syncthreads();
            // chain: z_{ph+1} = F_ph * TD + G_{ph+1}  (the only next-phase dependency)
            if (gw < 4096) {
                float a = warp_red(dot16<2048>(&h_F[ph][(size_t)gw * 1024], cur, lane));
                if (lane == 0) stf(&g_z[ph + 1][gw], a + ldf(&g_G[ph + 1][gw]));
            }
            bar_arrive(++ep);
            // background work overlaps the barrier propagation
            switch (ph) {
            case 0: bg_work(gw, lane, w8_Gtop, 1024, prv + 1024, g_G[4], d_gbase[4],
                            (t > 0) ? 1024 : 0, h_Vmid + (size_t)3 * 1024 * 1024, prv + 1024,
                            g_reconR[3], Vmid_b + 3072); break;
            case 1: bg_work(gw, lane, &w8_G[0][0], 2048, prv, g_G[0], d_gbase[0],
                            56, h_V1, prv + 1024, g_recon1, V1_b); break;
            case 2: bg_work(gw, lane, &w8_G[1][0], 2048, prv, g_G[1], d_gbase[1],
                            1024, h_Vmid, prv + 1024, g_reconR[0], Vmid_b); break;
            case 3: bg_work(gw, lane, &w8_G[2][0], 2048, prv, g_G[2], d_gbase[2],
                            1024, h_Vmid + (size_t)1024 * 1024, prv + 1024,
                            g_reconR[1], Vmid_b + 1024); break;
            }
            if (blockIdx.x == 0) {
                float s = block_sum(td, sred);
                if (tid == 0) stf(&g_loss_parts[t][1 + ph], s);
            }
            bar_wait(ep);
            pp ^= 1;
        }

        // ---- phase 4: top gates + z_0(t+1) ----
        {
            const bool more = (t + 1 < TT);
            __half* cur = &sbuf[pp][0];
            const __half* prv = &sbuf[pp ^ 1][0];
            {
                const int k = tid;
                float zi = ldf(&g_z[4][k]);
                float zf = ldf(&g_z[4][1024 + k]);
                float zg = ldf(&g_z[4][2048 + k]);
                float zo = ldf(&g_z[4][3072 + k]);
                float cn = sigm(zf) * c_reg[4] + sigm(zi) * tanhf(zg);
                c_reg[4] = cn;
                cur[1024 + k] = __float2half_rn(sigm(zo) * tanhf(cn));
            }
            float td0 = 0.f;
            if (more && tid < CC) {
                td0 = fabsf(x_seq[(t + 1) * CC + tid] - ldh(&g_recon1[tid]));
                sTD0[tid] = td0;
            }
            __syncthreads();
            if (more && gw < 4096) {
                float a = warp_red(dot56h(&h_F0[(size_t)gw * 64], sTD0, lane));
                if (lane == 0) stf(&g_z[0][gw], a + ldf(&g_G[0][gw]));
            }
            bar_arrive(++ep);
            bg_work(gw, lane, &w8_G[3][0], 2048, prv, g_G[3], d_gbase[3],
                    1024, h_Vmid + (size_t)2 * 1024 * 1024, prv + 1024,
                    g_reconR[2], Vmid_b + 2048);
            if (more && blockIdx.x == 0) {
                float s = block_sum(td0, sred);
                if (tid == 0) stf(&g_loss_parts[t + 1][0], s);
            }
            bar_wait(ep);
            pp ^= 1;
        }
    }

    // ---- epilogue: deterministic loss reduction ----
    if (blockIdx.x == 0) {
        const float* parts = &g_loss_parts[0][0];
        float v = 0.f;
        for (int i = tid; i < TT * 5; i += NTHR) v += ldf(&parts[i]);
        float s = block_sum(v, sred);
        if (tid == 0) out[0] = s;
    }
}

// ---------------- launch ---------------------------------------------------------
extern "C" void kernel_launch(void* const* d_in, const int* in_sizes, int n_in,
                              void* d_out, int out_size) {
    (void)in_sizes; (void)n_in; (void)out_size;
    const float* x_seq  = (const float*)d_in[0];
    const float* W0_w   = (const float*)d_in[1];
    const float* W0_b   = (const float*)d_in[2];
    const float* Wmid_w = (const float*)d_in[3];
    const float* Wmid_b = (const float*)d_in[4];
    const float* V1_w   = (const float*)d_in[5];
    const float* V1_b   = (const float*)d_in[6];
    const float* Vmid_w = (const float*)d_in[7];
    const float* Vmid_b = (const float*)d_in[8];
    const float* Wihm   = (const float*)d_in[9];
    const float* Whhm   = (const float*)d_in[10];
    const float* bmid   = (const float*)d_in[11];
    const float* Wiht   = (const float*)d_in[12];
    const float* Whht   = (const float*)d_in[13];
    const float* btop   = (const float*)d_in[14];

    conv_ab<<<2048, 256>>>(Wihm, Wiht, Wmid_w);
    gemm_fold_mma<<<dim3(16, 32, 4), 256>>>();
    f0_fold<<<512, 256>>>(Wihm, W0_w);
    gbase_kernel<<<2560, 256>>>(Wihm, Wiht, W0_b, Wmid_b, bmid, btop);
    convert_kernel<<<2048, 256>>>(V1_w, Vmid_w, Wihm, Whhm, Whht);
    predcells_kernel<<<NBLK, NTHR>>>(x_seq, V1_b, Vmid_b, (float*)d_out);
}